// round 8
// baseline (speedup 1.0000x reference)
#include <cuda_runtime.h>
#include <cuda_bf16.h>

#define N_FEAT 1024
#define RANK 4
#define SCALING 0.25f
#define TPB 256
#define ROWS_PER_CTA 16
#define NWARP 8
#define TOTAL_ROWS 32768

// scratch for h = SCALING * x @ A^T   [TOTAL_ROWS][RANK]
__device__ float4 g_h[TOTAL_ROWS];

// ─────────────────────────── Kernel 1: contraction ───────────────────────────
// Pure read stream: 64 KB of x per CTA -> 256 B of h.
__global__ __launch_bounds__(TPB) void lora_contract_kernel(
    const float* __restrict__ x,      // [M, 1024]
    const float* __restrict__ A)      // [4, 1024]
{
    const int t    = threadIdx.x;
    const int lane = t & 31;
    const int warp = t >> 5;
    const int row0 = blockIdx.x * ROWS_PER_CTA;

    __shared__ float red[NWARP][ROWS_PER_CTA][RANK];   // 2 KB

    // A resident in registers for the whole CTA
    const float4 a0 = reinterpret_cast<const float4*>(A + 0 * N_FEAT)[t];
    const float4 a1 = reinterpret_cast<const float4*>(A + 1 * N_FEAT)[t];
    const float4 a2 = reinterpret_cast<const float4*>(A + 2 * N_FEAT)[t];
    const float4 a3 = reinterpret_cast<const float4*>(A + 3 * N_FEAT)[t];

    const float4* xr = reinterpret_cast<const float4*>(x + (size_t)row0 * N_FEAT) + t;

    #pragma unroll
    for (int b = 0; b < ROWS_PER_CTA / 4; ++b) {
        float4 xv[4];
        #pragma unroll
        for (int i = 0; i < 4; ++i)
            xv[i] = xr[(size_t)(b * 4 + i) * (N_FEAT / 4)];

        #pragma unroll
        for (int i = 0; i < 4; ++i) {
            float p0 = xv[i].x * a0.x + xv[i].y * a0.y + xv[i].z * a0.z + xv[i].w * a0.w;
            float p1 = xv[i].x * a1.x + xv[i].y * a1.y + xv[i].z * a1.z + xv[i].w * a1.w;
            float p2 = xv[i].x * a2.x + xv[i].y * a2.y + xv[i].z * a2.z + xv[i].w * a2.w;
            float p3 = xv[i].x * a3.x + xv[i].y * a3.y + xv[i].z * a3.z + xv[i].w * a3.w;

            // rank-interleaved reduction: 6 shfls, lane L ends owning rank (L&3)
            float va = (lane & 1) ? p1 : p0;
            float vb = (lane & 1) ? p0 : p1;
            float vc = (lane & 1) ? p3 : p2;
            float vd = (lane & 1) ? p2 : p3;
            va += __shfl_xor_sync(0xFFFFFFFFu, vb, 1);
            vc += __shfl_xor_sync(0xFFFFFFFFu, vd, 1);
            float ve = (lane & 2) ? vc : va;
            float vf = (lane & 2) ? va : vc;
            ve += __shfl_xor_sync(0xFFFFFFFFu, vf, 2);
            ve += __shfl_xor_sync(0xFFFFFFFFu, ve, 4);
            ve += __shfl_xor_sync(0xFFFFFFFFu, ve, 8);
            ve += __shfl_xor_sync(0xFFFFFFFFu, ve, 16);

            if (lane < RANK)
                red[warp][b * 4 + i][lane] = ve;
        }
    }
    __syncthreads();

    // 64 threads: cross-warp sum, scale, store h
    if (t < ROWS_PER_CTA * RANK) {
        const int row  = t >> 2;
        const int rank = t & 3;
        float s = 0.f;
        #pragma unroll
        for (int w = 0; w < NWARP; ++w)
            s += red[w][row][rank];
        reinterpret_cast<float*>(&g_h[row0])[t] = s * SCALING;
    }
}

// ─────────────────────────── Kernel 2: expansion ───────────────────────────
// Pure write stream: 256 B of h (L2) -> 64 KB of out per CTA.
// No smem, no barrier, no shfl.
__global__ __launch_bounds__(TPB) void lora_expand_kernel(
    const float* __restrict__ B,      // [1024, 4]
    float* __restrict__ out)          // [M, 1024]
{
    const int t    = threadIdx.x;
    const int row0 = blockIdx.x * ROWS_PER_CTA;

    // B resident in registers: 4 consecutive output columns per thread
    const float4* Bv = reinterpret_cast<const float4*>(B);
    const float4 b0 = Bv[4 * t + 0];
    const float4 b1 = Bv[4 * t + 1];
    const float4 b2 = Bv[4 * t + 2];
    const float4 b3 = Bv[4 * t + 3];

    float4* outr = reinterpret_cast<float4*>(out + (size_t)row0 * N_FEAT) + t;

    #pragma unroll
    for (int r = 0; r < ROWS_PER_CTA; ++r) {
        const float4 h = __ldg(&g_h[row0 + r]);   // broadcast, L1/L2-hit
        float4 o;
        o.x = h.x * b0.x + h.y * b0.y + h.z * b0.z + h.w * b0.w;
        o.y = h.x * b1.x + h.y * b1.y + h.z * b1.z + h.w * b1.w;
        o.z = h.x * b2.x + h.y * b2.y + h.z * b2.z + h.w * b2.w;
        o.w = h.x * b3.x + h.y * b3.y + h.z * b3.z + h.w * b3.w;
        outr[(size_t)r * (N_FEAT / 4)] = o;
    }
}

extern "C" void kernel_launch(void* const* d_in, const int* in_sizes, int n_in,
                              void* d_out, int out_size)
{
    const float* x = (const float*)d_in[0];
    const float* A = (const float*)d_in[1];
    const float* B = (const float*)d_in[2];
    float* out = (float*)d_out;

    const int rows = in_sizes[0] / N_FEAT;   // 32768
    const int grid = rows / ROWS_PER_CTA;    // 2048

    lora_contract_kernel<<<grid, TPB>>>(x, A);
    lora_expand_kernel<<<grid, TPB>>>(B, out);
}

// round 10
// speedup vs baseline: 1.3970x; 1.3970x over previous
#include <cuda_runtime.h>
#include <cuda_bf16.h>

#define N_FEAT 1024
#define RANK 4
#define SCALING 0.25f
#define TPB 256           // 1024 floats / 4 per float4
#define ROWS_PER_CTA 16
#define BATCH 4
#define NWARP 8

__global__ __launch_bounds__(TPB) void lora_fused_kernel(
    const float* __restrict__ x,      // [M, 1024]
    const float* __restrict__ A,      // [4, 1024]
    const float* __restrict__ B,      // [1024, 4]
    float* __restrict__ out)          // [M, 1024]
{
    const int t    = threadIdx.x;
    const int lane = t & 31;
    const int warp = t >> 5;
    const int row0 = blockIdx.x * ROWS_PER_CTA;

    __shared__ float  red[NWARP][ROWS_PER_CTA][RANK];  // 2 KB
    __shared__ float4 h4[ROWS_PER_CTA];

    // ---- A resident in registers for the whole CTA (L1/L2 hits) ----
    const float4 a0 = reinterpret_cast<const float4*>(A + 0 * N_FEAT)[t];
    const float4 a1 = reinterpret_cast<const float4*>(A + 1 * N_FEAT)[t];
    const float4 a2 = reinterpret_cast<const float4*>(A + 2 * N_FEAT)[t];
    const float4 a3 = reinterpret_cast<const float4*>(A + 3 * N_FEAT)[t];

    const float4* xr = reinterpret_cast<const float4*>(x + (size_t)row0 * N_FEAT) + t;

    // ---- contraction: 4 batches of 4 rows ----
    #pragma unroll
    for (int b = 0; b < ROWS_PER_CTA / BATCH; ++b) {
        float4 xv[BATCH];
        #pragma unroll
        for (int i = 0; i < BATCH; ++i)
            xv[i] = __ldcs(&xr[(size_t)(b * BATCH + i) * (N_FEAT / 4)]);  // streaming

        #pragma unroll
        for (int i = 0; i < BATCH; ++i) {
            float p0 = xv[i].x * a0.x + xv[i].y * a0.y + xv[i].z * a0.z + xv[i].w * a0.w;
            float p1 = xv[i].x * a1.x + xv[i].y * a1.y + xv[i].z * a1.z + xv[i].w * a1.w;
            float p2 = xv[i].x * a2.x + xv[i].y * a2.y + xv[i].z * a2.z + xv[i].w * a2.w;
            float p3 = xv[i].x * a3.x + xv[i].y * a3.y + xv[i].z * a3.z + xv[i].w * a3.w;

            // rank-interleaved reduction: 6 shfls; lane L ends owning rank (L&3)
            float va = (lane & 1) ? p1 : p0;
            float vb = (lane & 1) ? p0 : p1;
            float vc = (lane & 1) ? p3 : p2;
            float vd = (lane & 1) ? p2 : p3;
            va += __shfl_xor_sync(0xFFFFFFFFu, vb, 1);
            vc += __shfl_xor_sync(0xFFFFFFFFu, vd, 1);
            float ve = (lane & 2) ? vc : va;
            float vf = (lane & 2) ? va : vc;
            ve += __shfl_xor_sync(0xFFFFFFFFu, vf, 2);
            ve += __shfl_xor_sync(0xFFFFFFFFu, ve, 4);
            ve += __shfl_xor_sync(0xFFFFFFFFu, ve, 8);
            ve += __shfl_xor_sync(0xFFFFFFFFu, ve, 16);

            if (lane < RANK)
                red[warp][b * BATCH + i][lane] = ve;
        }
    }
    __syncthreads();

    // ---- cross-warp finalize: 64 threads, one (row, rank) each ----
    if (t < ROWS_PER_CTA * RANK) {
        const int row  = t >> 2;
        const int rank = t & 3;
        float s = 0.f;
        #pragma unroll
        for (int w = 0; w < NWARP; ++w)
            s += red[w][row][rank];
        reinterpret_cast<float*>(h4)[t] = s * SCALING;
    }
    __syncthreads();

    // ---- expansion: B resident in registers, 16 output rows ----
    const float4* Bv = reinterpret_cast<const float4*>(B);   // B row j = one float4
    const float4 b0 = Bv[4 * t + 0];
    const float4 b1 = Bv[4 * t + 1];
    const float4 b2 = Bv[4 * t + 2];
    const float4 b3 = Bv[4 * t + 3];

    float4* outr = reinterpret_cast<float4*>(out + (size_t)row0 * N_FEAT) + t;
    #pragma unroll
    for (int r = 0; r < ROWS_PER_CTA; ++r) {
        const float4 h = h4[r];   // broadcast LDS.128
        float4 o;
        o.x = h.x * b0.x + h.y * b0.y + h.z * b0.z + h.w * b0.w;
        o.y = h.x * b1.x + h.y * b1.y + h.z * b1.z + h.w * b1.w;
        o.z = h.x * b2.x + h.y * b2.y + h.z * b2.z + h.w * b2.w;
        o.w = h.x * b3.x + h.y * b3.y + h.z * b3.z + h.w * b3.w;
        __stcs(&outr[(size_t)r * (N_FEAT / 4)], o);          // streaming store
    }
}

extern "C" void kernel_launch(void* const* d_in, const int* in_sizes, int n_in,
                              void* d_out, int out_size)
{
    const float* x = (const float*)d_in[0];
    const float* A = (const float*)d_in[1];
    const float* B = (const float*)d_in[2];
    float* out = (float*)d_out;

    const int rows = in_sizes[0] / N_FEAT;   // 32768
    lora_fused_kernel<<<rows / ROWS_PER_CTA, TPB>>>(x, A, B, out);
}